// round 8
// baseline (speedup 1.0000x reference)
#include <cuda_runtime.h>
#include <float.h>

// ---------------------------------------------------------------------------
// PointSIFT select_cube + group, fused 2-kernel pipeline.
//   k_build: per-batch block; smem histogram + warp-shuffle scan + scatter
//            (counting sort on 10^3 grid, cell size == radius).
//   k_query_gather: block = 256 threads = 8 queries. Each query is searched
//            by TWO 16-lane strips living in two different warps (strips
//            split the 4..9 z-spans by parity), winners merged via block-smem
//            atomicMin on 64-bit (dist_bits<<32 | j) keys. 8192 warps total
//            (was 4096 -> occupancy-starved). Gather: the block's 8 rows are
//            contiguous in gp, so all 256 threads stream coalesced scalar
//            stores directly (no smem staging).
//
// Output layout (float32, reference return order):
//   [0 .. BN*8*3)             grouped_xyz   [B,N,8,3]
//   [.. +BN*8*(3+C))          grouped_points[B,N,8,3+C]
//   [.. +BN*8)                idx (int32 cast to float) [B,N,8]
// ---------------------------------------------------------------------------

#define GRIDR   10
#define NCELL   (GRIDR*GRIDR*GRIDR)   // 1000
#define BMAX    2
#define NMAX    4096
#define PRADIUS 0.1f
#define QPB     8                     // queries per block (and warps per block)
#define CFEAT   64                    // feature channels (fixed by dataset)
#define FROW    (3 + CFEAT)           // 67
#define GPROW   (8 * FROW)            // 536 floats per query row

__device__ int    g_start [BMAX * (NCELL + 1)];
__device__ float4 g_sorted[BMAX * NMAX];   // x,y,z, w = bitcast(orig index)

__device__ __forceinline__ int cell_of(float x, float y, float z) {
    int cx = (int)(x * 10.0f); cx = min(max(cx, 0), GRIDR - 1);
    int cy = (int)(y * 10.0f); cy = min(max(cy, 0), GRIDR - 1);
    int cz = (int)(z * 10.0f); cz = min(max(cz, 0), GRIDR - 1);
    return (cx * GRIDR + cy) * GRIDR + cz;
}

// One block per batch. Histogram + warp-shuffle scan + scatter via smem.
__global__ __launch_bounds__(1024) void k_build(const float* __restrict__ xyz,
                                                int N) {
    __shared__ int s_cur [NCELL];
    __shared__ int s_wsum[32];

    int b   = blockIdx.x;
    int tid = threadIdx.x;
    int wid = tid >> 5;
    int lid = tid & 31;
    const float* xb = xyz + (size_t)b * N * 3;

    if (tid < NCELL) s_cur[tid] = 0;
    __syncthreads();

    const int PT = (NMAX + 1023) / 1024;   // 4
    float px[PT], py[PT], pz[PT];
    int   pc[PT];
    #pragma unroll
    for (int p = 0; p < PT; p++) {
        int i = tid + p * 1024;
        pc[p] = -1;
        if (i < N) {
            px[p] = xb[3 * i + 0];
            py[p] = xb[3 * i + 1];
            pz[p] = xb[3 * i + 2];
            pc[p] = cell_of(px[p], py[p], pz[p]);
            atomicAdd(&s_cur[pc[p]], 1);
        }
    }
    __syncthreads();

    int v = (tid < NCELL) ? s_cur[tid] : 0;
    int x = v;
    #pragma unroll
    for (int off = 1; off < 32; off <<= 1) {
        int y = __shfl_up_sync(0xFFFFFFFFu, x, off);
        if (lid >= off) x += y;
    }
    if (lid == 31) s_wsum[wid] = x;
    __syncthreads();
    if (wid == 0) {
        int y = s_wsum[lid];
        #pragma unroll
        for (int off = 1; off < 32; off <<= 1) {
            int z2 = __shfl_up_sync(0xFFFFFFFFu, y, off);
            if (lid >= off) y += z2;
        }
        s_wsum[lid] = y;
    }
    __syncthreads();
    int incl = x + (wid > 0 ? s_wsum[wid - 1] : 0);
    if (tid < NCELL) {
        int excl = incl - v;
        g_start[b * (NCELL + 1) + tid] = excl;
        s_cur[tid] = excl;
        if (tid == NCELL - 1)
            g_start[b * (NCELL + 1) + NCELL] = incl;
    }
    __syncthreads();

    float4* dst = g_sorted + (size_t)b * NMAX;
    #pragma unroll
    for (int p = 0; p < PT; p++) {
        if (pc[p] >= 0) {
            int pos = atomicAdd(&s_cur[pc[p]], 1);
            int i = tid + p * 1024;
            dst[pos] = make_float4(px[p], py[p], pz[p], __int_as_float(i));
        }
    }
}

// 8 queries per block; each query searched by two 16-lane strips (two warps).
__global__ __launch_bounds__(QPB * 32)
void k_query_gather(const float* __restrict__ xyz,
                    const float* __restrict__ pts,
                    float* __restrict__ gxyz,
                    float* __restrict__ gp,
                    float* __restrict__ idx_f,
                    int B, int N) {
    __shared__ unsigned long long s_key[QPB][8];
    __shared__ int                s_jj [QPB][8];

    const int tid    = threadIdx.x;
    const int w      = tid >> 5;
    const int lane   = tid & 31;
    const int h      = lane >> 4;          // half-warp id
    const int lane16 = lane & 15;
    const int strip  = w & 1;              // span-parity strip
    const int qb     = (w & ~1) + h;       // query slot in block (0..7)
    const int w0b    = blockIdx.x * QPB;   // first global query of block

    // init winner keys (seed: FLT_MAX dist, self index)
    if (tid < QPB * 8) {
        int q  = tid >> 3;
        int wq = w0b + q;
        int ii = wq - (wq / N) * N;
        s_key[q][tid & 7] =
            ((unsigned long long)0x7F7FFFFFull << 32) | (unsigned)ii;
    }
    __syncthreads();

    const int wq = w0b + qb;
    const int b  = wq / N;
    const int i  = wq - b * N;

    const float* xb = xyz + (size_t)b * N * 3;
    const float xi = xb[3 * i + 0], yi = xb[3 * i + 1], zi = xb[3 * i + 2];

    int cx = min(max((int)(xi * 10.0f), 0), GRIDR - 1);
    int cy = min(max((int)(yi * 10.0f), 0), GRIDR - 1);
    int cz = min(max((int)(zi * 10.0f), 0), GRIDR - 1);
    int ax0 = max(cx - 1, 0), ax1 = min(cx + 1, GRIDR - 1);
    int ay0 = max(cy - 1, 0), ay1 = min(cy + 1, GRIDR - 1);
    int az0 = max(cz - 1, 0), az1 = min(cz + 1, GRIDR - 1);
    int ny = ay1 - ay0 + 1;
    int ns = (ax1 - ax0 + 1) * ny;         // 4..9 spans

    const unsigned hm = 0xFFFFu << (h * 16);
    const int sbase = b * (NCELL + 1);
    const float4* __restrict__ srt = g_sorted + (size_t)b * NMAX;

    // prefetch all span ranges in parallel (lanes 0..ns-1 of this half)
    int rs = 0, re = 0;
    if (lane16 < ns) {
        int dxy = lane16 / ny;
        int axx = ax0 + dxy;
        int ayy = ay0 + lane16 - dxy * ny;
        int rowc = (axx * GRIDR + ayy) * GRIDR;
        rs = g_start[sbase + rowc + az0];
        re = g_start[sbase + rowc + az1 + 1];
    }

    // this strip handles spans strip, strip+2, ...
    for (int sp = strip; sp < ns; sp += 2) {
        int s0 = __shfl_sync(hm, rs, sp, 16);
        int e0 = __shfl_sync(hm, re, sp, 16);
        for (int k = s0 + lane16; k < e0; k += 16) {
            float4 p = srt[k];
            float dx = p.x - xi;
            float dy = p.y - yi;
            float dz = p.z - zi;
            if (fabsf(dx) < PRADIUS && fabsf(dy) < PRADIUS &&
                fabsf(dz) < PRADIUS) {
                unsigned j = (unsigned)__float_as_int(p.w);
                float d = __fadd_rn(
                    __fadd_rn(__fmul_rn(dx, dx), __fmul_rn(dy, dy)),
                    __fmul_rn(dz, dz));
                unsigned long long ck =
                    ((unsigned long long)(unsigned)__float_as_int(d) << 32) | j;
                int oct = ((dx > 0.0f) ? 4 : 0) |
                          ((dy > 0.0f) ? 2 : 0) |
                          ((dz > 0.0f) ? 1 : 0);
                atomicMin(&s_key[qb][oct], ck);
            }
        }
    }
    __syncthreads();

    // publish winners: 64 contiguous idx floats per block
    if (tid < QPB * 8) {
        int j = (int)(unsigned)(s_key[tid >> 3][tid & 7] & 0xFFFFFFFFull);
        s_jj[tid >> 3][tid & 7] = j;
        idx_f[(size_t)w0b * 8 + tid] = (float)j;
    }
    __syncthreads();

    // gather/write: block's gp region is one contiguous run of 8*536 floats.
    {
        float* gpo = gp + (size_t)w0b * GPROW;
        #pragma unroll
        for (int e = tid; e < QPB * GPROW; e += QPB * 32) {
            int q  = e / GPROW;
            int r  = e - q * GPROW;
            int o  = r / FROW;
            int c  = r - o * FROW;
            int wq2 = w0b + q;
            int b2  = wq2 / N;
            int i2  = wq2 - b2 * N;
            int jj  = s_jj[q][o];
            float vv;
            if (c < 3) {
                const float* xb2 = xyz + (size_t)b2 * N * 3;
                vv = xb2[3 * jj + c] - xb2[3 * i2 + c];
            } else {
                vv = pts[(size_t)b2 * N * CFEAT + (size_t)jj * CFEAT + (c - 3)];
            }
            gpo[e] = vv;
        }
    }
    // gxyz: 8 queries x 24 floats = 192 contiguous floats
    if (tid < QPB * 24) {
        int q = tid / 24;
        int r = tid - q * 24;
        int o = r / 3;
        int c = r - o * 3;
        int wq2 = w0b + q;
        int b2  = wq2 / N;
        int i2  = wq2 - b2 * N;
        int jj  = s_jj[q][o];
        const float* xb2 = xyz + (size_t)b2 * N * 3;
        gxyz[(size_t)w0b * 24 + tid] = xb2[3 * jj + c] - xb2[3 * i2 + c];
    }
}

extern "C" void kernel_launch(void* const* d_in, const int* in_sizes, int n_in,
                              void* d_out, int out_size) {
    const float* xyz = (const float*)d_in[0];
    const float* pts = (const float*)d_in[1];
    float* out = (float*)d_out;

    int BN = in_sizes[0] / 3;       // B*N = 8192
    int B  = 2;
    int N  = BN / B;                // 4096

    size_t nG = (size_t)BN * 8;
    float* gxyz  = out;
    float* gp    = out + nG * 3;
    float* idx_f = out + nG * 3 + nG * (size_t)FROW;

    k_build<<<B, 1024>>>(xyz, N);
    k_query_gather<<<(BN + QPB - 1) / QPB, QPB * 32>>>(
        xyz, pts, gxyz, gp, idx_f, B, N);
}

// round 9
// speedup vs baseline: 1.4000x; 1.4000x over previous
#include <cuda_runtime.h>
#include <float.h>

// ---------------------------------------------------------------------------
// PointSIFT select_cube + group, fused 2-kernel pipeline.
//   k_build: per-batch block; smem histogram + warp-shuffle scan + scatter
//            (counting sort on 10^3 grid, cell size == radius).
//   k_query_gather: block = 256 threads = 8 queries.
//     Search: each query served by TWO 16-lane strips in two paired warps
//       (strips split the 4..9 z-spans by parity); winners merged via block
//       smem atomicMin on 64-bit (dist_bits<<32 | j) keys. 8192 warps total.
//     Gather: warp q owns query q; features via float4 loads staged in smem,
//       final write-out as aligned float4 stores. No per-element int division.
//
// Output layout (float32, reference return order):
//   [0 .. BN*8*3)             grouped_xyz   [B,N,8,3]
//   [.. +BN*8*(3+C))          grouped_points[B,N,8,3+C]
//   [.. +BN*8)                idx (int32 cast to float) [B,N,8]
// ---------------------------------------------------------------------------

#define GRIDR   10
#define NCELL   (GRIDR*GRIDR*GRIDR)   // 1000
#define BMAX    2
#define NMAX    4096
#define PRADIUS 0.1f
#define QPB     8                     // queries per block == warps per block
#define CFEAT   64
#define FROW    (3 + CFEAT)           // 67
#define GPROW   (8 * FROW)            // 536 floats per query row

__device__ int    g_start [BMAX * (NCELL + 1)];
__device__ float4 g_sorted[BMAX * NMAX];   // x,y,z, w = bitcast(orig index)

__device__ __forceinline__ int cell_of(float x, float y, float z) {
    int cx = (int)(x * 10.0f); cx = min(max(cx, 0), GRIDR - 1);
    int cy = (int)(y * 10.0f); cy = min(max(cy, 0), GRIDR - 1);
    int cz = (int)(z * 10.0f); cz = min(max(cz, 0), GRIDR - 1);
    return (cx * GRIDR + cy) * GRIDR + cz;
}

// One block per batch. Histogram + warp-shuffle scan + scatter via smem.
__global__ __launch_bounds__(1024) void k_build(const float* __restrict__ xyz,
                                                int N) {
    __shared__ int s_cur [NCELL];
    __shared__ int s_wsum[32];

    int b   = blockIdx.x;
    int tid = threadIdx.x;
    int wid = tid >> 5;
    int lid = tid & 31;
    const float* xb = xyz + (size_t)b * N * 3;

    if (tid < NCELL) s_cur[tid] = 0;
    __syncthreads();

    const int PT = (NMAX + 1023) / 1024;   // 4
    float px[PT], py[PT], pz[PT];
    int   pc[PT];
    #pragma unroll
    for (int p = 0; p < PT; p++) {
        int i = tid + p * 1024;
        pc[p] = -1;
        if (i < N) {
            px[p] = xb[3 * i + 0];
            py[p] = xb[3 * i + 1];
            pz[p] = xb[3 * i + 2];
            pc[p] = cell_of(px[p], py[p], pz[p]);
            atomicAdd(&s_cur[pc[p]], 1);
        }
    }
    __syncthreads();

    int v = (tid < NCELL) ? s_cur[tid] : 0;
    int x = v;
    #pragma unroll
    for (int off = 1; off < 32; off <<= 1) {
        int y = __shfl_up_sync(0xFFFFFFFFu, x, off);
        if (lid >= off) x += y;
    }
    if (lid == 31) s_wsum[wid] = x;
    __syncthreads();
    if (wid == 0) {
        int y = s_wsum[lid];
        #pragma unroll
        for (int off = 1; off < 32; off <<= 1) {
            int z2 = __shfl_up_sync(0xFFFFFFFFu, y, off);
            if (lid >= off) y += z2;
        }
        s_wsum[lid] = y;
    }
    __syncthreads();
    int incl = x + (wid > 0 ? s_wsum[wid - 1] : 0);
    if (tid < NCELL) {
        int excl = incl - v;
        g_start[b * (NCELL + 1) + tid] = excl;
        s_cur[tid] = excl;
        if (tid == NCELL - 1)
            g_start[b * (NCELL + 1) + NCELL] = incl;
    }
    __syncthreads();

    float4* dst = g_sorted + (size_t)b * NMAX;
    #pragma unroll
    for (int p = 0; p < PT; p++) {
        if (pc[p] >= 0) {
            int pos = atomicAdd(&s_cur[pc[p]], 1);
            int i = tid + p * 1024;
            dst[pos] = make_float4(px[p], py[p], pz[p], __int_as_float(i));
        }
    }
}

// 8 queries/block; search = 2 strips x 16 lanes per query; gather = warp/query.
__global__ __launch_bounds__(QPB * 32)
void k_query_gather(const float* __restrict__ xyz,
                    const float* __restrict__ pts,
                    float* __restrict__ gxyz,
                    float* __restrict__ gp,
                    float* __restrict__ idx_f,
                    int B, int N) {
    __shared__ unsigned long long   s_key  [QPB][8];
    __shared__ int                  s_jj   [QPB][8];
    __shared__ alignas(16) float    s_stage[QPB][GPROW];  // 8 x 536
    __shared__ alignas(16) float    s_gx   [QPB][24];

    const int tid    = threadIdx.x;
    const int w      = tid >> 5;
    const int lane   = tid & 31;
    const int h      = lane >> 4;          // half-warp id
    const int lane16 = lane & 15;
    const int strip  = w & 1;              // span-parity strip
    const int qb     = (w & ~1) + h;       // query slot in block (0..7)
    const int w0b    = blockIdx.x * QPB;   // first global query of block

    // block never straddles a batch (N % QPB == 0): one div per thread
    const int b  = w0b / N;
    const int i0 = w0b - b * N;
    const float* xb = xyz + (size_t)b * N * 3;

    // init winner keys (seed: FLT_MAX dist, self index)
    if (tid < QPB * 8) {
        s_key[tid >> 3][tid & 7] =
            ((unsigned long long)0x7F7FFFFFull << 32)
            | (unsigned)(i0 + (tid >> 3));
    }
    __syncthreads();

    // ---------------- search ----------------
    const int i  = i0 + qb;
    const float xi = xb[3 * i + 0], yi = xb[3 * i + 1], zi = xb[3 * i + 2];

    int cx = min(max((int)(xi * 10.0f), 0), GRIDR - 1);
    int cy = min(max((int)(yi * 10.0f), 0), GRIDR - 1);
    int cz = min(max((int)(zi * 10.0f), 0), GRIDR - 1);
    int ax0 = max(cx - 1, 0), ax1 = min(cx + 1, GRIDR - 1);
    int ay0 = max(cy - 1, 0), ay1 = min(cy + 1, GRIDR - 1);
    int az0 = max(cz - 1, 0), az1 = min(cz + 1, GRIDR - 1);
    int ny = ay1 - ay0 + 1;
    int ns = (ax1 - ax0 + 1) * ny;         // 4..9 spans

    const unsigned hm = 0xFFFFu << (h * 16);
    const int sbase = b * (NCELL + 1);
    const float4* __restrict__ srt = g_sorted + (size_t)b * NMAX;

    // prefetch all span ranges in parallel (lanes 0..ns-1 of this half)
    int rs = 0, re = 0;
    if (lane16 < ns) {
        int dxy = lane16 / ny;
        int axx = ax0 + dxy;
        int ayy = ay0 + lane16 - dxy * ny;
        int rowc = (axx * GRIDR + ayy) * GRIDR;
        rs = g_start[sbase + rowc + az0];
        re = g_start[sbase + rowc + az1 + 1];
    }

    for (int sp = strip; sp < ns; sp += 2) {
        int s0 = __shfl_sync(hm, rs, sp, 16);
        int e0 = __shfl_sync(hm, re, sp, 16);
        for (int k = s0 + lane16; k < e0; k += 16) {
            float4 p = srt[k];
            float dx = p.x - xi;
            float dy = p.y - yi;
            float dz = p.z - zi;
            if (fabsf(dx) < PRADIUS && fabsf(dy) < PRADIUS &&
                fabsf(dz) < PRADIUS) {
                unsigned j = (unsigned)__float_as_int(p.w);
                float d = __fadd_rn(
                    __fadd_rn(__fmul_rn(dx, dx), __fmul_rn(dy, dy)),
                    __fmul_rn(dz, dz));
                unsigned long long ck =
                    ((unsigned long long)(unsigned)__float_as_int(d) << 32) | j;
                int oct = ((dx > 0.0f) ? 4 : 0) |
                          ((dy > 0.0f) ? 2 : 0) |
                          ((dz > 0.0f) ? 1 : 0);
                atomicMin(&s_key[qb][oct], ck);
            }
        }
    }
    __syncthreads();

    // publish winners: 64 contiguous idx floats per block
    if (tid < QPB * 8) {
        int j = (int)(unsigned)(s_key[tid >> 3][tid & 7] & 0xFFFFFFFFull);
        s_jj[tid >> 3][tid & 7] = j;
        idx_f[(size_t)w0b * 8 + tid] = (float)j;
    }
    __syncthreads();

    // ---------------- gather: warp w owns query (w0b + w) ----------------
    const int iq = i0 + w;                        // this warp's query index

    // centered xyz: 24 values (lanes 0..23)
    if (lane < 24) {
        int o = lane / 3;
        int c = lane - o * 3;
        int jj = s_jj[w][o];
        float v = xb[3 * jj + c] - xb[3 * iq + c];
        s_stage[w][o * FROW + c] = v;
        s_gx[w][lane] = v;
    }

    // features: 8 octants x 16 float4 = 128 vector loads, 4 dense iterations
    const float4* __restrict__ pb4 =
        (const float4*)(pts + (size_t)b * N * CFEAT);
    #pragma unroll
    for (int t0 = 0; t0 < 4; t0++) {
        int t  = lane + t0 * 32;     // 0..127
        int o  = t >> 4;
        int q  = t & 15;
        int jj = s_jj[w][o];
        float4 f4 = pb4[(size_t)jj * 16 + q];
        int base = o * FROW + 3 + q * 4;
        s_stage[w][base + 0] = f4.x;
        s_stage[w][base + 1] = f4.y;
        s_stage[w][base + 2] = f4.z;
        s_stage[w][base + 3] = f4.w;
    }
    __syncwarp();

    // write-out: 536 floats = 134 aligned float4 per query row
    float4*       gpo = (float4*)(gp + (size_t)(w0b + w) * GPROW);
    const float4* st4 = (const float4*)s_stage[w];
    #pragma unroll
    for (int f = lane; f < GPROW / 4; f += 32)
        gpo[f] = st4[f];
    if (lane < 6)
        ((float4*)(gxyz + (size_t)(w0b + w) * 24))[lane] =
            ((const float4*)s_gx[w])[lane];
}

extern "C" void kernel_launch(void* const* d_in, const int* in_sizes, int n_in,
                              void* d_out, int out_size) {
    const float* xyz = (const float*)d_in[0];
    const float* pts = (const float*)d_in[1];
    float* out = (float*)d_out;

    int BN = in_sizes[0] / 3;       // B*N = 8192
    int B  = 2;
    int N  = BN / B;                // 4096

    size_t nG = (size_t)BN * 8;
    float* gxyz  = out;
    float* gp    = out + nG * 3;
    float* idx_f = out + nG * 3 + nG * (size_t)FROW;

    k_build<<<B, 1024>>>(xyz, N);
    k_query_gather<<<(BN + QPB - 1) / QPB, QPB * 32>>>(
        xyz, pts, gxyz, gp, idx_f, B, N);
}